// round 6
// baseline (speedup 1.0000x reference)
#include <cuda_runtime.h>

// MBTR + analytic divergence, GB300 (sm_103a). Round 5 (fix of R4):
//  - 4 grid points per thread (ILP x4, LDS amortized x4)
//  - exp2f with direct tt-form (precision-safe): E = exp2(cm*tt*tt)
//  - mbtr via global atomicAdd; block pre-zeroes ALL its 256 exclusive
//    cells with a strided loop (R4 bug: only 192 of 256 were zeroed ->
//    accumulation across graph replays)
//
// Pair (i,j): d=|ri-rj|, gf=1/d, wf=exp(-d), u=(ri-rj)/d, gfs=gf/sigma
//   tt=(g-gf)/sigma, gv=C*exp(-tt^2/2), C=dx/(sqrt(2pi)*sigma)
//   mbtr[b,zi,zj,g] += wf*gv
//   div at atom a from partner j (both orientations): -s*u_aj,
//     s = wf*gv*(1 + (gf^2/sigma)*tt)
// Slot (e1,e2) at atom a: (e1==za)*acc[e2] + (e2==za)*acc[e1].

#define NB     32
#define NA     48
#define NE     4
#define NG     128
#define LAYERS 4
#define NGT    4                   // grid points per thread
#define GPB    (LAYERS * NGT)      // 16
#define NCHUNK (NG / GPB)          // 8
#define NTHR   (NA * LAYERS)       // 192

#define DIV_SLOT_STRIDE (NG * NA * 3)
#define DIV_G_STRIDE    (NA * 3)

__global__ void __launch_bounds__(NTHR, 4)
mbtr_kernel(const float* __restrict__ r,
            const int*   __restrict__ z,
            const float* __restrict__ grid,
            float*       __restrict__ out)
{
    const int b  = blockIdx.x / NCHUNK;
    const int gc = blockIdx.x - b * NCHUNK;
    const int t  = threadIdx.x;
    const int a  = t % NA;
    const int l  = t / NA;

    __shared__ float4 tabA[NA][NA];      // {gfs, wf*C, gsq, -ux}
    __shared__ float2 tabB[NA][NA];      // {-uy, -uz}
    __shared__ float4 rs[NA];
    __shared__ int    zs[NA], S[NA], segs[NE + 1];

    const float INV_SIGMA = 20.0f;
    const float CM        = -0.72134752044448170f;   // -0.5 * log2(e)

    if (t < NA) {
        zs[t] = z[t];
        const float* rp = r + (b * NA + t) * 3;
        rs[t] = make_float4(rp[0], rp[1], rp[2], 0.f);
    }

    // Zero ALL of this block's exclusive mbtr cells (256 > NTHR -> strided).
    for (int i = t; i < NE * NE * GPB; i += NTHR) {
        const int slot = i / GPB, gi = i - slot * GPB;
        out[((size_t)b * NE * NE + slot) * NG + gc * GPB + gi] = 0.f;
    }
    __syncthreads();

    if (t == 0) {
        int cnt[NE] = {0, 0, 0, 0};
        for (int j = 0; j < NA; j++) cnt[zs[j]]++;
        int off = 0, pos[NE];
        segs[0] = 0;
        #pragma unroll
        for (int e = 0; e < NE; e++) { pos[e] = off; off += cnt[e]; segs[e + 1] = off; }
        for (int j = 0; j < NA; j++) S[pos[zs[j]]++] = j;
    }
    __syncthreads();

    // Pair-table fill: 2304 pairs over 192 threads.
    {
        const float gdx = grid[1] - grid[0];
        const float C   = gdx * 0.3989422804014327f * INV_SIGMA;
        #pragma unroll
        for (int it = 0; it < (NA * NA) / NTHR; it++) {
            const int idx = it * NTHR + t;
            const int jp = idx / NA;
            const int a2 = idx - jp * NA;
            const int p  = S[jp];
            if (p == a2) {
                tabA[jp][a2] = make_float4(0.f, 0.f, 0.f, 0.f);
                tabB[jp][a2] = make_float2(0.f, 0.f);
            } else {
                const float4 ra = rs[a2], rp = rs[p];
                const float dx = ra.x - rp.x, dy = ra.y - rp.y, dz = ra.z - rp.z;
                const float d2   = fmaf(dx, dx, fmaf(dy, dy, dz * dz));
                const float invd = rsqrtf(d2);
                const float d    = d2 * invd;
                const float wf   = __expf(-d);
                tabA[jp][a2] = make_float4(invd * INV_SIGMA, wf * C,
                                           invd * invd * INV_SIGMA, -dx * invd);
                tabB[jp][a2] = make_float2(-dy * invd, -dz * invd);
            }
        }
    }
    __syncthreads();

    const int za = zs[a];

    // This thread's 4 grid points: g_k = gc*GPB + l + k*LAYERS.
    float gg[NGT];
    #pragma unroll
    for (int k = 0; k < NGT; k++)
        gg[k] = grid[gc * GPB + l + k * LAYERS] * INV_SIGMA;

    float* __restrict__ dout = out + (NB * NE * NE * NG);
    float* const pbase = dout + ((size_t)b * NE * NE * NG + gc * GPB + l) * DIV_G_STRIDE + a * 3;

    #pragma unroll
    for (int e = 0; e < NE; e++) {
        float w[NGT], x[NGT], y[NGT], zc[NGT];
        #pragma unroll
        for (int k = 0; k < NGT; k++) { w[k] = 0.f; x[k] = 0.f; y[k] = 0.f; zc[k] = 0.f; }

        const int j0 = segs[e], j1e = segs[e + 1];
        for (int jp = j0; jp < j1e; jp++) {
            const float4 A  = tabA[jp][a];
            const float2 Bv = tabB[jp][a];
            #pragma unroll
            for (int k = 0; k < NGT; k++) {
                const float tt = gg[k] - A.x;              // (g - gf)/sigma
                const float E  = exp2f((CM * tt) * tt);
                const float wg = A.y * E;                  // wf*gv
                const float s  = fmaf(wg * A.z, tt, wg);
                w[k] += wg;
                x[k]  = fmaf(s, A.w,  x[k]);
                y[k]  = fmaf(s, Bv.x, y[k]);
                zc[k] = fmaf(s, Bv.y, zc[k]);
            }
        }

        // mbtr: global reduction into this block's pre-zeroed cells.
        #pragma unroll
        for (int k = 0; k < NGT; k++) {
            const int g = gc * GPB + l + k * LAYERS;
            atomicAdd(&out[((size_t)b * NE * NE + za * NE + e) * NG + g], w[k]);
        }

        // Nonzero div slots for this segment.
        if (e == za) {
            float* q = pbase + (za * NE + za) * DIV_SLOT_STRIDE;
            #pragma unroll
            for (int k = 0; k < NGT; k++) {
                float* qk = q + k * LAYERS * DIV_G_STRIDE;
                qk[0] = 2.f * x[k]; qk[1] = 2.f * y[k]; qk[2] = 2.f * zc[k];
            }
        } else {
            float* qa = pbase + (za * NE + e) * DIV_SLOT_STRIDE;
            float* qb = pbase + (e * NE + za) * DIV_SLOT_STRIDE;
            #pragma unroll
            for (int k = 0; k < NGT; k++) {
                float* qk = qa + k * LAYERS * DIV_G_STRIDE;
                qk[0] = x[k]; qk[1] = y[k]; qk[2] = zc[k];
                qk = qb + k * LAYERS * DIV_G_STRIDE;
                qk[0] = x[k]; qk[1] = y[k]; qk[2] = zc[k];
            }
        }
    }

    // Zero slots (za not involved): dependency-free epilogue.
    #pragma unroll
    for (int e1 = 0; e1 < NE; e1++) {
        #pragma unroll
        for (int e2 = 0; e2 < NE; e2++) {
            if (e1 != za && e2 != za) {
                float* q = pbase + (e1 * NE + e2) * DIV_SLOT_STRIDE;
                #pragma unroll
                for (int k = 0; k < NGT; k++) {
                    float* qk = q + k * LAYERS * DIV_G_STRIDE;
                    qk[0] = 0.f; qk[1] = 0.f; qk[2] = 0.f;
                }
            }
        }
    }
}

extern "C" void kernel_launch(void* const* d_in, const int* in_sizes, int n_in,
                              void* d_out, int out_size)
{
    const float* r    = (const float*)d_in[0];
    const int*   z    = (const int*)  d_in[1];
    const float* grid = (const float*)d_in[2];
    float*       out  = (float*)d_out;

    mbtr_kernel<<<NB * NCHUNK, NTHR>>>(r, z, grid, out);
}